// round 2
// baseline (speedup 1.0000x reference)
#include <cuda_runtime.h>
#include <math.h>

// Problem constants (fixed by the dataset)
#define BCNT 16
#define QLEN 4096
#define KLEN 4096
#define DIM  256
#define NQROWS (BCNT*QLEN)   // 65536
#define NKROWS (BCNT*KLEN)   // 65536

// ---------------- scratch (static device globals; no allocs allowed) ------------
__device__ float g_qp [NQROWS*DIM];      // phi(q)  64 MB
__device__ float g_kp [NKROWS*DIM];      // phi(k)  64 MB
__device__ float g_nq [NQROWS];          // per-row exponent offset for q
__device__ float g_nk [NKROWS];          // per-row exponent offset for k
__device__ float g_b1v[BCNT*DIM*DIM];    // buf1 value part  [b][m][c]
__device__ float g_b1s[BCNT*DIM];        // buf1 ones column [b][m]
__device__ float g_den[NQROWS];          // denominator per q row

// ---------------- row norms: s[r] = -0.03125*||row||^2 - ln(16) ---------------
// (x = row * 0.25  =>  -0.5*||x||^2 = -0.03125*||row||^2 ; 1/sqrt(m)=1/16)
__global__ void rownorm_kernel(const float* __restrict__ X, int which /*0=q,1=k*/) {
    int warp = (blockIdx.x * blockDim.x + threadIdx.x) >> 5;
    int lane = threadIdx.x & 31;
    const float4* row = (const float4*)(X + (size_t)warp * DIM);
    float4 a = row[lane * 2];
    float4 b = row[lane * 2 + 1];
    float s = a.x*a.x + a.y*a.y + a.z*a.z + a.w*a.w
            + b.x*b.x + b.y*b.y + b.z*b.z + b.w*b.w;
    #pragma unroll
    for (int o = 16; o; o >>= 1) s += __shfl_xor_sync(0xFFFFFFFFu, s, o);
    if (lane == 0) {
        float v = -0.03125f * s - 2.7725887222397811f;
        if (which) g_nk[warp] = v; else g_nq[warp] = v;
    }
}

// ---------------- phi GEMM: out[r][n] = exp(0.25*dot(X[r],proj[n]) + s[r]) -----
// 128x128 tile, BK=16, 256 threads, 8x8 micro-tile.
__global__ void __launch_bounds__(256) phi_gemm(const float* __restrict__ X,
                                                const float* __restrict__ proj,
                                                int which /*0=q,1=k*/) {
    __shared__ float As[16 * 132];
    __shared__ float Bs[16 * 132];
    const int tid = threadIdx.x;
    const int tx  = tid & 15;
    const int ty  = tid >> 4;
    const int row0 = blockIdx.y * 128;
    const int col0 = blockIdx.x * 128;

    float acc[8][8];
    #pragma unroll
    for (int i = 0; i < 8; i++)
        #pragma unroll
        for (int j = 0; j < 8; j++) acc[i][j] = 0.f;

    for (int k0 = 0; k0 < DIM; k0 += 16) {
        #pragma unroll
        for (int l = 0; l < 2; l++) {
            int idx = tid + l * 256;          // 0..511
            int r   = idx >> 2;               // 0..127
            int kq  = (idx & 3) * 4;          // 0,4,8,12
            float4 va = *(const float4*)(X    + (size_t)(row0 + r) * DIM + k0 + kq);
            As[(kq+0)*132 + r] = va.x;
            As[(kq+1)*132 + r] = va.y;
            As[(kq+2)*132 + r] = va.z;
            As[(kq+3)*132 + r] = va.w;
            float4 vb = *(const float4*)(proj + (size_t)(col0 + r) * DIM + k0 + kq);
            Bs[(kq+0)*132 + r] = vb.x;
            Bs[(kq+1)*132 + r] = vb.y;
            Bs[(kq+2)*132 + r] = vb.z;
            Bs[(kq+3)*132 + r] = vb.w;
        }
        __syncthreads();
        #pragma unroll
        for (int kk = 0; kk < 16; kk++) {
            float a[8], b[8];
            float4 t;
            t = *(const float4*)&As[kk*132 + ty*8    ]; a[0]=t.x; a[1]=t.y; a[2]=t.z; a[3]=t.w;
            t = *(const float4*)&As[kk*132 + ty*8 + 4]; a[4]=t.x; a[5]=t.y; a[6]=t.z; a[7]=t.w;
            t = *(const float4*)&Bs[kk*132 + tx*8    ]; b[0]=t.x; b[1]=t.y; b[2]=t.z; b[3]=t.w;
            t = *(const float4*)&Bs[kk*132 + tx*8 + 4]; b[4]=t.x; b[5]=t.y; b[6]=t.z; b[7]=t.w;
            #pragma unroll
            for (int i = 0; i < 8; i++)
                #pragma unroll
                for (int j = 0; j < 8; j++)
                    acc[i][j] = fmaf(a[i], b[j], acc[i][j]);
        }
        __syncthreads();
    }

    float* out = which ? g_kp : g_qp;
    const float* nrm = which ? g_nk : g_nq;
    #pragma unroll
    for (int i = 0; i < 8; i++) {
        int r = row0 + ty*8 + i;
        float s = nrm[r];
        #pragma unroll
        for (int j = 0; j < 8; j++) {
            out[(size_t)r * DIM + col0 + tx*8 + j] = expf(0.25f * acc[i][j] + s);
        }
    }
}

// ---------------- zero buf1 scratch --------------------------------------------
__global__ void zero_kernel() {
    int n1 = BCNT * DIM * DIM;
    int n2 = BCNT * DIM;
    for (int i = blockIdx.x * blockDim.x + threadIdx.x; i < n1; i += gridDim.x * blockDim.x)
        g_b1v[i] = 0.f;
    for (int i = blockIdx.x * blockDim.x + threadIdx.x; i < n2; i += gridDim.x * blockDim.x)
        g_b1s[i] = 0.f;
}

// ---------------- buf1_v[b][m][c] += sum_{k<valid} kp[b][k][m]*vs[b][k][c] -----
// grid: x = 16 tiles (mt*4+ct, 64x64), y = batch, z = ksplit(8, chunks of 512)
__global__ void __launch_bounds__(256) buf1_kernel(const float* __restrict__ vs,
                                                   const int*   __restrict__ vlen) {
    __shared__ float As[16 * 68];
    __shared__ float Bs[16 * 68];
    const int b  = blockIdx.y;
    const int ks = blockIdx.z;
    const int m0 = (blockIdx.x >> 2) * 64;
    const int c0 = (blockIdx.x &  3) * 64;
    const int kbeg = ks * 512;
    const int kend = min(vlen[b], kbeg + 512);
    if (kbeg >= kend) return;

    const int tid = threadIdx.x;
    const int tx  = tid & 15;
    const int ty  = tid >> 4;
    const float* kpb = g_kp + (size_t)b * KLEN * DIM;
    const float* vsb = vs   + (size_t)b * KLEN * DIM;

    float acc[4][4];
    #pragma unroll
    for (int i = 0; i < 4; i++)
        #pragma unroll
        for (int j = 0; j < 4; j++) acc[i][j] = 0.f;

    const int kl = tid >> 4;          // 0..15 (k within tile)
    const int mq = (tid & 15) * 4;    // 0..60

    for (int k0 = kbeg; k0 < kend; k0 += 16) {
        int gk = k0 + kl;
        float4 va, vb;
        if (gk < kend) {
            va = *(const float4*)(kpb + (size_t)gk * DIM + m0 + mq);
            vb = *(const float4*)(vsb + (size_t)gk * DIM + c0 + mq);
        } else {
            va = make_float4(0.f,0.f,0.f,0.f);
            vb = make_float4(0.f,0.f,0.f,0.f);
        }
        *(float4*)&As[kl*68 + mq] = va;
        *(float4*)&Bs[kl*68 + mq] = vb;
        __syncthreads();
        #pragma unroll
        for (int kk = 0; kk < 16; kk++) {
            float4 a4 = *(const float4*)&As[kk*68 + ty*4];
            float4 b4 = *(const float4*)&Bs[kk*68 + tx*4];
            float a[4] = {a4.x, a4.y, a4.z, a4.w};
            float bb[4] = {b4.x, b4.y, b4.z, b4.w};
            #pragma unroll
            for (int i = 0; i < 4; i++)
                #pragma unroll
                for (int j = 0; j < 4; j++)
                    acc[i][j] = fmaf(a[i], bb[j], acc[i][j]);
        }
        __syncthreads();
    }
    #pragma unroll
    for (int i = 0; i < 4; i++)
        #pragma unroll
        for (int j = 0; j < 4; j++)
            atomicAdd(&g_b1v[((size_t)b * DIM + m0 + ty*4 + i) * DIM + c0 + tx*4 + j],
                      acc[i][j]);
}

// ---------------- buf1_s[b][m] += sum_{k<valid} kp[b][k][m] -------------------
__global__ void buf1s_kernel(const int* __restrict__ vlen) {
    const int b  = blockIdx.y;
    const int ks = blockIdx.x;
    const int m  = threadIdx.x;
    const int kbeg = ks * 512;
    const int kend = min(vlen[b], kbeg + 512);
    if (kbeg >= kend) return;
    const float* kpb = g_kp + (size_t)b * KLEN * DIM;
    float acc = 0.f;
    for (int k = kbeg; k < kend; k++)
        acc += kpb[(size_t)k * DIM + m];
    atomicAdd(&g_b1s[b * DIM + m], acc);
}

// ---------------- den[r] = dot(qp[r], b1s[b]) ---------------------------------
__global__ void den_kernel() {
    int warp = (blockIdx.x * blockDim.x + threadIdx.x) >> 5;
    int lane = threadIdx.x & 31;
    int b = warp >> 12;   // 4096 rows per batch
    const float4* q4 = (const float4*)(g_qp + (size_t)warp * DIM);
    const float4* s4 = (const float4*)(g_b1s + b * DIM);
    float4 qa = q4[lane*2],   qb = q4[lane*2+1];
    float4 sa = s4[lane*2],   sb = s4[lane*2+1];
    float s = qa.x*sa.x + qa.y*sa.y + qa.z*sa.z + qa.w*sa.w
            + qb.x*sb.x + qb.y*sb.y + qb.z*sb.z + qb.w*sb.w;
    #pragma unroll
    for (int o = 16; o; o >>= 1) s += __shfl_xor_sync(0xFFFFFFFFu, s, o);
    if (lane == 0) g_den[warp] = s;
}

// ---------------- ctx GEMM: out[r][c] = dot(qp[r], b1v[b][:,c]) / den[r] -------
__global__ void __launch_bounds__(256) ctx_gemm(float* __restrict__ out) {
    __shared__ float As[16 * 132];
    __shared__ float Bs[16 * 132];
    const int tid = threadIdx.x;
    const int tx  = tid & 15;
    const int ty  = tid >> 4;
    const int row0 = blockIdx.y * 128;
    const int col0 = blockIdx.x * 128;
    const int b = row0 >> 12;
    const float* Bm = g_b1v + (size_t)b * DIM * DIM;

    float acc[8][8];
    #pragma unroll
    for (int i = 0; i < 8; i++)
        #pragma unroll
        for (int j = 0; j < 8; j++) acc[i][j] = 0.f;

    for (int k0 = 0; k0 < DIM; k0 += 16) {
        #pragma unroll
        for (int l = 0; l < 2; l++) {
            int idx = tid + l * 256;
            // A tile (transpose into smem)
            int r  = idx >> 2;
            int kq = (idx & 3) * 4;
            float4 va = *(const float4*)(g_qp + (size_t)(row0 + r) * DIM + k0 + kq);
            As[(kq+0)*132 + r] = va.x;
            As[(kq+1)*132 + r] = va.y;
            As[(kq+2)*132 + r] = va.z;
            As[(kq+3)*132 + r] = va.w;
            // B tile (row-major direct)
            int kb = idx >> 5;            // 0..15
            int nq = (idx & 31) * 4;      // 0..124
            float4 vb = *(const float4*)(Bm + (size_t)(k0 + kb) * DIM + col0 + nq);
            *(float4*)&Bs[kb*132 + nq] = vb;
        }
        __syncthreads();
        #pragma unroll
        for (int kk = 0; kk < 16; kk++) {
            float a[8], bb[8];
            float4 t;
            t = *(const float4*)&As[kk*132 + ty*8    ]; a[0]=t.x; a[1]=t.y; a[2]=t.z; a[3]=t.w;
            t = *(const float4*)&As[kk*132 + ty*8 + 4]; a[4]=t.x; a[5]=t.y; a[6]=t.z; a[7]=t.w;
            t = *(const float4*)&Bs[kk*132 + tx*8    ]; bb[0]=t.x; bb[1]=t.y; bb[2]=t.z; bb[3]=t.w;
            t = *(const float4*)&Bs[kk*132 + tx*8 + 4]; bb[4]=t.x; bb[5]=t.y; bb[6]=t.z; bb[7]=t.w;
            #pragma unroll
            for (int i = 0; i < 8; i++)
                #pragma unroll
                for (int j = 0; j < 8; j++)
                    acc[i][j] = fmaf(a[i], bb[j], acc[i][j]);
        }
        __syncthreads();
    }
    #pragma unroll
    for (int i = 0; i < 8; i++) {
        int r = row0 + ty*8 + i;
        float d = g_den[r];
        #pragma unroll
        for (int j = 0; j < 8; j++) {
            out[(size_t)r * DIM + col0 + tx*8 + j] = acc[i][j] / d;
        }
    }
}

// ---------------- launch -------------------------------------------------------
extern "C" void kernel_launch(void* const* d_in, const int* in_sizes, int n_in,
                              void* d_out, int out_size) {
    (void)in_sizes; (void)n_in; (void)out_size;
    const float* qs   = (const float*)d_in[0];
    const float* ks   = (const float*)d_in[1];
    const float* vs   = (const float*)d_in[2];
    const int*   vlen = (const int*)  d_in[3];
    const float* proj = (const float*)d_in[4];
    float* out = (float*)d_out;

    // 1) per-row exponent offsets
    rownorm_kernel<<<NQROWS/8, 256>>>(qs, 0);
    rownorm_kernel<<<NKROWS/8, 256>>>(ks, 1);

    // 2) phi projections (dominant GEMMs)
    phi_gemm<<<dim3(DIM/128, NQROWS/128), 256>>>(qs, proj, 0);
    phi_gemm<<<dim3(DIM/128, NKROWS/128), 256>>>(ks, proj, 1);

    // 3) zero split-K accumulators (fresh every replay)
    zero_kernel<<<1024, 256>>>();

    // 4) buf1 reductions over valid k
    buf1_kernel<<<dim3(16, BCNT, 8), 256>>>(vs, vlen);
    buf1s_kernel<<<dim3(8, BCNT), 256>>>(vlen);

    // 5) denominators
    den_kernel<<<NQROWS/8, 256>>>();

    // 6) final context GEMM + divide
    ctx_gemm<<<dim3(DIM/128, NQROWS/128), 256>>>(out);
}

// round 4
// speedup vs baseline: 1.7251x; 1.7251x over previous
#include <cuda_runtime.h>
#include <cuda_bf16.h>
#include <cstdint>

#define BCNT 16
#define QLEN 4096
#define KLEN 4096
#define DIM  256
#define NQROWS (BCNT*QLEN)
#define NKROWS (BCNT*KLEN)

// ---------------- scratch ----------------
__device__ __nv_bfloat16 g_qp_hi[NQROWS*DIM];   // phi(q) hi [r][m]
__device__ __nv_bfloat16 g_qp_lo[NQROWS*DIM];
__device__ __nv_bfloat16 g_kp_hi[NKROWS*DIM];   // phi(k) hi [b*4096+k][m]
__device__ __nv_bfloat16 g_kp_lo[NKROWS*DIM];
__device__ float g_nq[NQROWS];
__device__ float g_nk[NKROWS];
__device__ float g_b1v[BCNT*DIM*DIM];           // fp32 [b][m][c]
__device__ __nv_bfloat16 g_b1h[BCNT*DIM*DIM];   // bf16 split of b1v
__device__ __nv_bfloat16 g_b1l[BCNT*DIM*DIM];
__device__ float g_b1s[BCNT*DIM];               // ones-column sums
__device__ float g_den[NQROWS];

// ---------------- helpers ----------------
static __device__ __forceinline__ uint32_t smem_u32(const void* p){
  uint32_t a;
  asm("{ .reg .u64 t; cvta.to.shared.u64 t, %1; cvt.u32.u64 %0, t; }" : "=r"(a) : "l"(p));
  return a;
}
static __device__ __forceinline__ void ldsm4(uint32_t* r, uint32_t a){
  asm volatile("ldmatrix.sync.aligned.m8n8.x4.shared.b16 {%0,%1,%2,%3}, [%4];"
    : "=r"(r[0]),"=r"(r[1]),"=r"(r[2]),"=r"(r[3]) : "r"(a));
}
static __device__ __forceinline__ void ldsm4t(uint32_t* r, uint32_t a){
  asm volatile("ldmatrix.sync.aligned.m8n8.x4.trans.shared.b16 {%0,%1,%2,%3}, [%4];"
    : "=r"(r[0]),"=r"(r[1]),"=r"(r[2]),"=r"(r[3]) : "r"(a));
}
static __device__ __forceinline__ void mma_bf16(float* c, const uint32_t* a, const uint32_t* b){
  asm volatile("mma.sync.aligned.m16n8k16.row.col.f32.bf16.bf16.f32 "
    "{%0,%1,%2,%3}, {%4,%5,%6,%7}, {%8,%9}, {%0,%1,%2,%3};"
    : "+f"(c[0]),"+f"(c[1]),"+f"(c[2]),"+f"(c[3])
    : "r"(a[0]),"r"(a[1]),"r"(a[2]),"r"(a[3]), "r"(b[0]),"r"(b[1]));
}
static __device__ __forceinline__ float fast_exp(float x){
  float t = fmaxf(x * 1.4426950408889634f, -125.0f);
  float j = t + 12582912.0f;
  int   ji = __float_as_int(j);
  float f  = t - (j - 12582912.0f);
  float p = 1.33333694e-3f;
  p = fmaf(p, f, 9.61812910e-3f);
  p = fmaf(p, f, 5.55041087e-2f);
  p = fmaf(p, f, 2.40226507e-1f);
  p = fmaf(p, f, 6.93147181e-1f);
  p = fmaf(p, f, 1.0f);
  return __int_as_float(__float_as_int(p) + (ji << 23));
}
static __device__ __forceinline__ void split2(float a, float b, uint32_t& hp, uint32_t& lp){
  __nv_bfloat16 ha = __float2bfloat16(a), hb = __float2bfloat16(b);
  __nv_bfloat16 la = __float2bfloat16(a - __bfloat162float(ha));
  __nv_bfloat16 lb = __float2bfloat16(b - __bfloat162float(hb));
  hp = (uint32_t)__bfloat16_as_ushort(ha) | ((uint32_t)__bfloat16_as_ushort(hb)<<16);
  lp = (uint32_t)__bfloat16_as_ushort(la) | ((uint32_t)__bfloat16_as_ushort(lb)<<16);
}

// ---------------- row norms ----------------
__global__ void rownorm_kernel(const float* __restrict__ X, int which){
  int warp = (blockIdx.x * blockDim.x + threadIdx.x) >> 5;
  int lane = threadIdx.x & 31;
  const float4* row = (const float4*)(X + (size_t)warp * DIM);
  float4 a = row[lane*2], b = row[lane*2+1];
  float s = a.x*a.x+a.y*a.y+a.z*a.z+a.w*a.w + b.x*b.x+b.y*b.y+b.z*b.z+b.w*b.w;
  #pragma unroll
  for (int o = 16; o; o >>= 1) s += __shfl_xor_sync(0xFFFFFFFFu, s, o);
  if (lane == 0){
    float v = -0.03125f*s - 2.7725887222397811f;
    if (which) g_nk[warp] = v; else g_nq[warp] = v;
  }
}

__global__ void zero_kernel(){
  for (int i = blockIdx.x*blockDim.x + threadIdx.x; i < BCNT*DIM*DIM; i += gridDim.x*blockDim.x)
    g_b1v[i] = 0.f;
  for (int i = blockIdx.x*blockDim.x + threadIdx.x; i < BCNT*DIM; i += gridDim.x*blockDim.x)
    g_b1s[i] = 0.f;
}

// ---------------- phi: C = X @ proj^T, epilogue exp; which=1 also folds b1s ----
__global__ void __launch_bounds__(256) phi_mma(const float* __restrict__ X,
                                               const float* __restrict__ proj,
                                               const int* __restrict__ vlen,
                                               int which)
{
  __shared__ __align__(16) char sm[40960];
  const int AH=0, AL=10240, BH=20480, BL=30720;   // 128 rows x 80B each
  const int tid = threadIdx.x, lane = tid & 31, wid = tid >> 5;
  const int wm = wid & 3, wn = wid >> 2;          // 4 x 2 warp grid
  const int row0 = blockIdx.y * 128, col0 = blockIdx.x * 128;
  const uint32_t sb = smem_u32(sm);

  float acc[2][8][4];
  #pragma unroll
  for (int i = 0; i < 2; i++)
    #pragma unroll
    for (int j = 0; j < 8; j++)
      #pragma unroll
      for (int k = 0; k < 4; k++) acc[i][j][k] = 0.f;

  const int lr = tid >> 1, lc = (tid & 1) * 16;
  const int a_r = (lane&7) + ((lane>>3)&1)*8, a_c16 = (lane>>4)*16;
  const int b_r = (lane&7) + (lane>>4)*8,     b_c16 = ((lane>>3)&1)*16;

  for (int k0 = 0; k0 < DIM; k0 += 32){
    const float* s1 = X    + (size_t)(row0+lr)*DIM + k0 + lc;
    const float* s2 = proj + (size_t)(col0+lr)*DIM + k0 + lc;
    uint32_t off = lr*80 + lc*2;
    #pragma unroll
    for (int q = 0; q < 4; q++){
      float4 v = *(const float4*)(s1 + q*4);
      uint32_t h0,l0,h1,l1; split2(v.x,v.y,h0,l0); split2(v.z,v.w,h1,l1);
      *(uint32_t*)(sm+AH+off+q*8) = h0; *(uint32_t*)(sm+AH+off+q*8+4) = h1;
      *(uint32_t*)(sm+AL+off+q*8) = l0; *(uint32_t*)(sm+AL+off+q*8+4) = l1;
      v = *(const float4*)(s2 + q*4);
      split2(v.x,v.y,h0,l0); split2(v.z,v.w,h1,l1);
      *(uint32_t*)(sm+BH+off+q*8) = h0; *(uint32_t*)(sm+BH+off+q*8+4) = h1;
      *(uint32_t*)(sm+BL+off+q*8) = l0; *(uint32_t*)(sm+BL+off+q*8+4) = l1;
    }
    __syncthreads();
    #pragma unroll
    for (int h = 0; h < 2; h++){
      uint32_t ah[2][4], al[2][4], bh[4][4], bl[4][4];
      #pragma unroll
      for (int mi = 0; mi < 2; mi++){
        uint32_t ad = sb + AH + (uint32_t)(wm*32 + mi*16 + a_r)*80 + a_c16 + h*32;
        ldsm4(ah[mi], ad);
        ldsm4(al[mi], ad + (AL-AH));
      }
      #pragma unroll
      for (int ng = 0; ng < 4; ng++){
        uint32_t bd = sb + BH + (uint32_t)(wn*64 + ng*16 + b_r)*80 + b_c16 + h*32;
        ldsm4(bh[ng], bd);
        ldsm4(bl[ng], bd + (BL-BH));
      }
      #pragma unroll
      for (int mi = 0; mi < 2; mi++)
        #pragma unroll
        for (int ng = 0; ng < 4; ng++){
          mma_bf16(acc[mi][ng*2],   ah[mi], &bh[ng][0]);
          mma_bf16(acc[mi][ng*2+1], ah[mi], &bh[ng][2]);
        }
      #pragma unroll
      for (int mi = 0; mi < 2; mi++)
        #pragma unroll
        for (int ng = 0; ng < 4; ng++){
          mma_bf16(acc[mi][ng*2],   ah[mi], &bl[ng][0]);
          mma_bf16(acc[mi][ng*2+1], ah[mi], &bl[ng][2]);
        }
      #pragma unroll
      for (int mi = 0; mi < 2; mi++)
        #pragma unroll
        for (int ng = 0; ng < 4; ng++){
          mma_bf16(acc[mi][ng*2],   al[mi], &bh[ng][0]);
          mma_bf16(acc[mi][ng*2+1], al[mi], &bh[ng][2]);
        }
    }
    __syncthreads();
  }

  const int l4 = lane >> 2, l2 = (lane & 3) * 2;
  if (which == 0){
    #pragma unroll
    for (int mi = 0; mi < 2; mi++){
      int r0 = row0 + wm*32 + mi*16 + l4;
      float s0 = g_nq[r0], s1 = g_nq[r0+8];
      #pragma unroll
      for (int nj = 0; nj < 8; nj++){
        int col = col0 + wn*64 + nj*8 + l2;
        float* c = acc[mi][nj];
        float v00 = fast_exp(fmaf(0.25f, c[0], s0));
        float v01 = fast_exp(fmaf(0.25f, c[1], s0));
        float v10 = fast_exp(fmaf(0.25f, c[2], s1));
        float v11 = fast_exp(fmaf(0.25f, c[3], s1));
        uint32_t h, l;
        split2(v00, v01, h, l);
        *(uint32_t*)&g_qp_hi[(size_t)r0*DIM+col] = h;
        *(uint32_t*)&g_qp_lo[(size_t)r0*DIM+col] = l;
        split2(v10, v11, h, l);
        *(uint32_t*)&g_qp_hi[(size_t)(r0+8)*DIM+col] = h;
        *(uint32_t*)&g_qp_lo[(size_t)(r0+8)*DIM+col] = l;
      }
    }
  } else {
    const int b = row0 >> 12;
    const int vl = vlen[b];
    float s0a[2], s1a[2];
    #pragma unroll
    for (int mi = 0; mi < 2; mi++){
      int r0 = row0 + wm*32 + mi*16 + l4;
      s0a[mi] = g_nk[r0]; s1a[mi] = g_nk[r0+8];
    }
    #pragma unroll
    for (int nj = 0; nj < 8; nj++){
      int col = col0 + wn*64 + nj*8 + l2;
      float cs0 = 0.f, cs1 = 0.f;
      #pragma unroll
      for (int mi = 0; mi < 2; mi++){
        int r0 = row0 + wm*32 + mi*16 + l4;
        float* c = acc[mi][nj];
        float v00 = fast_exp(fmaf(0.25f, c[0], s0a[mi]));
        float v01 = fast_exp(fmaf(0.25f, c[1], s0a[mi]));
        float v10 = fast_exp(fmaf(0.25f, c[2], s1a[mi]));
        float v11 = fast_exp(fmaf(0.25f, c[3], s1a[mi]));
        uint32_t h, l;
        split2(v00, v01, h, l);
        *(uint32_t*)&g_kp_hi[(size_t)r0*DIM+col] = h;
        *(uint32_t*)&g_kp_lo[(size_t)r0*DIM+col] = l;
        split2(v10, v11, h, l);
        *(uint32_t*)&g_kp_hi[(size_t)(r0+8)*DIM+col] = h;
        *(uint32_t*)&g_kp_lo[(size_t)(r0+8)*DIM+col] = l;
        int k0i = r0 & 4095, k1i = k0i + 8;
        cs0 += (k0i < vl ? v00 : 0.f) + (k1i < vl ? v10 : 0.f);
        cs1 += (k0i < vl ? v01 : 0.f) + (k1i < vl ? v11 : 0.f);
      }
      #pragma unroll
      for (int o = 4; o <= 16; o <<= 1){
        cs0 += __shfl_xor_sync(0xFFFFFFFFu, cs0, o);
        cs1 += __shfl_xor_sync(0xFFFFFFFFu, cs1, o);
      }
      if (lane < 4){
        atomicAdd(&g_b1s[b*DIM + col], cs0);
        atomicAdd(&g_b1s[b*DIM + col + 1], cs1);
      }
    }
  }
}

// ---------------- buf1: b1v[b][m][c] += sum_k kp[k][m]*v[k][c], split-K ----------
__global__ void __launch_bounds__(256) buf1_mma(const float* __restrict__ vs,
                                                const int* __restrict__ vlen)
{
  __shared__ __align__(16) char sm[34816];
  const int AH=0, AL=8704, BH=17408, BL=26112;    // 32 rows x 272B each
  const int b  = blockIdx.y;
  const int m0 = (blockIdx.x >> 1) * 128, c0 = (blockIdx.x & 1) * 128;
  const int kbeg = blockIdx.z * 1024;
  const int kend = min(vlen[b], kbeg + 1024);
  if (kbeg >= kend) return;
  const int tid = threadIdx.x, lane = tid & 31, wid = tid >> 5;
  const int wm = wid & 3, wn = wid >> 2;
  const uint32_t sb = smem_u32(sm);

  float acc[2][8][4];
  #pragma unroll
  for (int i = 0; i < 2; i++)
    #pragma unroll
    for (int j = 0; j < 8; j++)
      #pragma unroll
      for (int k = 0; k < 4; k++) acc[i][j][k] = 0.f;

  const int lkr = tid >> 3;
  const int lmu = (tid & 7) * 8;      // u32 col for A
  const int lcb = (tid & 7) * 16;     // fp32 col for B
  const int at_k = (lane&7) + (lane>>4)*8,      at_m16 = ((lane>>3)&1)*16;
  const int bt_k = (lane&7) + ((lane>>3)&1)*8,  bt_c16 = (lane>>4)*16;

  for (int k0 = kbeg; k0 < kend; k0 += 32){
    const bool ok = (k0 + lkr) < kend;
    {
      size_t base = ((size_t)(b*KLEN + k0 + lkr))*DIM + m0;
      const uint4* sh = (const uint4*)((const uint32_t*)(g_kp_hi + base) + lmu);
      const uint4* sl = (const uint4*)((const uint32_t*)(g_kp_lo + base) + lmu);
      uint4 z = make_uint4(0,0,0,0);
      uint4 h0 = ok ? sh[0] : z, h1 = ok ? sh[1] : z;
      uint4 l0 = ok ? sl[0] : z, l1 = ok ? sl[1] : z;
      uint32_t off = lkr*272 + lmu*4;
      *(uint4*)(sm+AH+off) = h0; *(uint4*)(sm+AH+off+16) = h1;
      *(uint4*)(sm+AL+off) = l0; *(uint4*)(sm+AL+off+16) = l1;
    }
    {
      const float* src = vs + ((size_t)b*KLEN + k0 + lkr)*DIM + c0 + lcb;
      uint32_t off = lkr*272 + lcb*2;
      #pragma unroll
      for (int q = 0; q < 4; q++){
        float4 v = ok ? *(const float4*)(src + q*4) : make_float4(0.f,0.f,0.f,0.f);
        uint32_t h0,l0,h1,l1; split2(v.x,v.y,h0,l0); split2(v.z,v.w,h1,l1);
        *(uint32_t*)(sm+BH+off+q*8) = h0; *(uint32_t*)(sm+BH+off+q*8+4) = h1;
        *(uint32_t*)(sm+BL+off+q*8) = l0; *(uint32_t*)(sm+BL+off+q*8+4) = l1;
      }
    }
    __syncthreads();
    #pragma unroll
    for (int h = 0; h < 2; h++){
      uint32_t ah[2][4], al[2][4], bh[4][4], bl[4][4];
      #pragma unroll
      for (int mi = 0; mi < 2; mi++){
        uint32_t ad = sb + AH + (uint32_t)(h*16 + at_k)*272 + (uint32_t)(wm*32 + mi*16)*2 + at_m16;
        ldsm4t(ah[mi], ad);
        ldsm4t(al[mi], ad + (AL-AH));
      }
      #pragma unroll
      for (int ng = 0; ng < 4; ng++){
        uint32_t bd = sb + BH + (uint32_t)(h*16 + bt_k)*272 + (uint32_t)(wn*64 + ng*16)*2 + bt_c16;
        ldsm4t(bh[ng], bd);
        ldsm4t(bl[ng], bd + (BL-BH));
      }
      #pragma unroll
      for (int mi = 0; mi < 2; mi++)
        #pragma unroll
        for (int ng = 0; ng < 4; ng++){
          mma_bf16(acc[mi][ng*2],   ah[mi], &bh[ng][0]);
          mma_bf16(acc[mi][ng*2+1], ah[mi], &bh[ng][2]);
        }
      #pragma unroll
      for (int mi = 0; mi < 2; mi++)
        #pragma unroll
        for (int ng = 0; ng < 4; ng++){
          mma_bf16(acc[mi][ng*2],   ah[mi], &bl[ng][0]);
          mma_bf16(acc[mi][ng*2+1], ah[mi], &bl[ng][2]);
        }
      #pragma unroll
      for (int mi = 0; mi < 2; mi++)
        #pragma unroll
        for (int ng = 0; ng < 4; ng++){
          mma_bf16(acc[mi][ng*2],   al[mi], &bh[ng][0]);
          mma_bf16(acc[mi][ng*2+1], al[mi], &bh[ng][2]);
        }
    }
    __syncthreads();
  }

  const int l4 = lane >> 2, l2 = (lane & 3) * 2;
  #pragma unroll
  for (int mi = 0; mi < 2; mi++){
    int m = m0 + wm*32 + mi*16 + l4;
    #pragma unroll
    for (int nj = 0; nj < 8; nj++){
      int col = c0 + wn*64 + nj*8 + l2;
      float* c = acc[mi][nj];
      atomicAdd(&g_b1v[((size_t)(b*DIM + m))*DIM + col],     c[0]);
      atomicAdd(&g_b1v[((size_t)(b*DIM + m))*DIM + col + 1], c[1]);
      atomicAdd(&g_b1v[((size_t)(b*DIM + m + 8))*DIM + col],     c[2]);
      atomicAdd(&g_b1v[((size_t)(b*DIM + m + 8))*DIM + col + 1], c[3]);
    }
  }
}

// ---------------- b1v fp32 -> bf16 hi/lo ----------------
__global__ void b1split(){
  for (int j = blockIdx.x*blockDim.x + threadIdx.x; j < BCNT*DIM*DIM; j += gridDim.x*blockDim.x){
    float v = g_b1v[j];
    __nv_bfloat16 h = __float2bfloat16(v);
    g_b1h[j] = h;
    g_b1l[j] = __float2bfloat16(v - __bfloat162float(h));
  }
}

// ---------------- den[r] = dot(qp[r], b1s[b]) ----------------
__global__ void den_tc(){
  int warp = (blockIdx.x * blockDim.x + threadIdx.x) >> 5;
  int lid = threadIdx.x & 31;
  int b = warp >> 12;
  const __nv_bfloat16* qh = g_qp_hi + (size_t)warp*DIM + lid*8;
  const __nv_bfloat16* ql = g_qp_lo + (size_t)warp*DIM + lid*8;
  const float* bs = g_b1s + b*DIM + lid*8;
  float s = 0.f;
  #pragma unroll
  for (int t = 0; t < 8; t++)
    s += (__bfloat162float(qh[t]) + __bfloat162float(ql[t])) * bs[t];
  #pragma unroll
  for (int o = 16; o; o >>= 1) s += __shfl_xor_sync(0xFFFFFFFFu, s, o);
  if (lid == 0) g_den[warp] = s;
}

// ---------------- ctx: out[r][c] = (qp[r] . b1[:,c]) / den[r] ----------------
__global__ void __launch_bounds__(256) ctx_mma(float* __restrict__ out)
{
  __shared__ __align__(16) char sm[37888];
  const int AH=0, AL=10240, BH=20480, BL=29184;
  const int tid = threadIdx.x, lane = tid & 31, wid = tid >> 5;
  const int wm = wid & 3, wn = wid >> 2;
  const int row0 = blockIdx.y * 128, c0 = blockIdx.x * 128;
  const int b = row0 >> 12;
  const uint32_t sb = smem_u32(sm);

  float acc[2][8][4];
  #pragma unroll
  for (int i = 0; i < 2; i++)
    #pragma unroll
    for (int j = 0; j < 8; j++)
      #pragma unroll
      for (int k = 0; k < 4; k++) acc[i][j][k] = 0.f;

  const int lr = tid >> 1, lmu = (tid & 1) * 8;   // A load
  const int mr = tid >> 3, cu = (tid & 7) * 8;    // B load
  const int a_r = (lane&7) + ((lane>>3)&1)*8, a_c16 = (lane>>4)*16;
  const int bt_k = (lane&7) + ((lane>>3)&1)*8, bt_c16 = (lane>>4)*16;

  for (int k0 = 0; k0 < DIM; k0 += 32){
    {
      size_t base = (size_t)(row0 + lr)*DIM + k0;
      const uint4* sh = (const uint4*)((const uint32_t*)(g_qp_hi + base) + lmu);
      const uint4* sl = (const uint4*)((const uint32_t*)(g_qp_lo + base) + lmu);
      uint32_t off = lr*80 + lmu*4;
      *(uint4*)(sm+AH+off) = sh[0]; *(uint4*)(sm+AH+off+16) = sh[1];
      *(uint4*)(sm+AL+off) = sl[0]; *(uint4*)(sm+AL+off+16) = sl[1];
    }
    {
      size_t base = ((size_t)(b*DIM + k0 + mr))*DIM + c0;
      const uint4* sh = (const uint4*)((const uint32_t*)(g_b1h + base) + cu);
      const uint4* sl = (const uint4*)((const uint32_t*)(g_b1l + base) + cu);
      uint32_t off = mr*272 + cu*4;
      *(uint4*)(sm+BH+off) = sh[0]; *(uint4*)(sm+BH+off+16) = sh[1];
      *(uint4*)(sm+BL+off) = sl[0]; *(uint4*)(sm+BL+off+16) = sl[1];
    }
    __syncthreads();
    #pragma unroll
    for (int h = 0; h < 2; h++){
      uint32_t ah[2][4], al[2][4], bh[4][4], bl[4][4];
      #pragma unroll
      for (int mi = 0; mi < 2; mi++){
        uint32_t ad = sb + AH + (uint32_t)(wm*32 + mi*16 + a_r)*80 + a_c16 + h*32;
        ldsm4(ah[mi], ad);
        ldsm4(al[mi], ad + (AL-AH));
      }
      #pragma unroll
      for (int ng = 0; ng < 4; ng++){
        uint32_t bd = sb + BH + (uint32_t)(h*16 + bt_k)*272 + (uint32_t)(wn*64 + ng*16)*2 + bt_c16;
        ldsm4t(bh[ng], bd);
        ldsm4t(bl[ng], bd + (BL-BH));
      }
      #pragma unroll
      for (int mi = 0; mi < 2; mi++)
        #pragma unroll
        for (int ng = 0; ng < 4; ng++){
          mma_bf16(acc[mi][ng*2],   ah[mi], &bh[ng][0]);
          mma_bf16(acc[mi][ng*2+1], ah[mi], &bh[ng][2]);
        }
      #pragma unroll
      for (int mi = 0; mi < 2; mi++)
        #pragma unroll
        for (int ng = 0; ng < 4; ng++){
          mma_bf16(acc[mi][ng*2],   ah[mi], &bl[ng][0]);
          mma_bf16(acc[mi][ng*2+1], ah[mi], &bl[ng][2]);
        }
      #pragma unroll
      for (int mi = 0; mi < 2; mi++)
        #pragma unroll
        for (int ng = 0; ng < 4; ng++){
          mma_bf16(acc[mi][ng*2],   al[mi], &bh[ng][0]);
          mma_bf16(acc[mi][ng*2+1], al[mi], &bh[ng][2]);
        }
    }
    __syncthreads();
  }

  const int l4 = lane >> 2, l2 = (lane & 3) * 2;
  #pragma unroll
  for (int mi = 0; mi < 2; mi++){
    int r0 = row0 + wm*32 + mi*16 + l4;
    float i0 = 1.0f / g_den[r0];
    float i1 = 1.0f / g_den[r0+8];
    #pragma unroll
    for (int nj = 0; nj < 8; nj++){
      int col = c0 + wn*64 + nj*8 + l2;
      float* c = acc[mi][nj];
      float2 v0 = make_float2(c[0]*i0, c[1]*i0);
      float2 v1 = make_float2(c[2]*i1, c[3]*i1);
      *(float2*)(out + (size_t)r0*DIM + col) = v0;
      *(float2*)(out + (size_t)(r0+8)*DIM + col) = v1;
    }
  }
}

// ---------------- launch ----------------
extern "C" void kernel_launch(void* const* d_in, const int* in_sizes, int n_in,
                              void* d_out, int out_size) {
  (void)in_sizes; (void)n_in; (void)out_size;
  const float* qs   = (const float*)d_in[0];
  const float* ks   = (const float*)d_in[1];
  const float* vs   = (const float*)d_in[2];
  const int*   vlen = (const int*)  d_in[3];
  const float* proj = (const float*)d_in[4];
  float* out = (float*)d_out;

  rownorm_kernel<<<NQROWS/8, 256>>>(qs, 0);
  rownorm_kernel<<<NKROWS/8, 256>>>(ks, 1);
  zero_kernel<<<256, 256>>>();

  phi_mma<<<dim3(2, NQROWS/128), 256>>>(qs, proj, vlen, 0);
  phi_mma<<<dim3(2, NKROWS/128), 256>>>(ks, proj, vlen, 1);

  buf1_mma<<<dim3(4, BCNT, 4), 256>>>(vs, vlen);
  b1split<<<1024, 256>>>();
  den_tc<<<NQROWS/8, 256>>>();

  ctx_mma<<<dim3(2, NQROWS/128), 256>>>(out);
}